// round 12
// baseline (speedup 1.0000x reference)
#include <cuda_runtime.h>
#include <cuda_bf16.h>

// CenterLoss: loss = mean_b sum_d (features[b,d] - centers[labels[b],d])^2
// B=65536, D=256, C=100000. HBM-bound gather + reduction.
// Stage1 (147 SMs x 8 CTAs): proven R5 mainloop (__ldcs features, pipelined
//   labels). PDL trigger at ENTRY; each CTA publishes partial + release-flag.
// Stage2 (1 CTA on the reserved 148th SM): LOW-RATE polling — relaxed load +
//   __nanosleep backoff (R8's tight acquire-spin stole LTS bandwidth from
//   stage1), single acquire fence on success. Tail = poll cadence, not launch.

#define BATCH    65536
#define FEAT_DIM 256
#define GRID1    1176          // 147 SMs * 8 CTAs — one SM left free for stage2
#define BLOCK1   256           // 8 warps per CTA
#define NWARPS   ((GRID1 * BLOCK1) >> 5)   // 9408

__device__ __align__(16) float g_partials[GRID1];
__device__ int g_flags[GRID1];             // zero-initialized at module load

__device__ __forceinline__ void store_release_gpu_i(int* p, int v) {
    asm volatile("st.global.release.gpu.s32 [%0], %1;" :: "l"(p), "r"(v) : "memory");
}
__device__ __forceinline__ int load_relaxed_i(const int* p) {
    int v;
    asm volatile("ld.global.relaxed.gpu.s32 %0, [%1];" : "=r"(v) : "l"(p) : "memory");
    return v;
}
__device__ __forceinline__ void fence_acquire_gpu() {
    asm volatile("fence.acquire.gpu;" ::: "memory");
}

__global__ __launch_bounds__(BLOCK1, 8) void center_loss_stage1(
    const float* __restrict__ features,
    const int*   __restrict__ labels,
    const float* __restrict__ centers)
{
    // Fire the dependent launch immediately: stage2 starts (sleep-polling).
    cudaTriggerProgrammaticLaunchCompletion();

    const int lane   = threadIdx.x & 31;
    const int wid    = threadIdx.x >> 5;
    const int warp_g = (blockIdx.x * BLOCK1 + threadIdx.x) >> 5;

    float acc = 0.0f;

    int row = warp_g;
    int lbl = (row < BATCH) ? __ldcs(labels + row) : 0;   // pipelined label

    for (; row < BATCH; ) {
        const int next_row = row + NWARPS;
        const int next_lbl = (next_row < BATCH) ? __ldcs(labels + next_row) : 0;

        const float4* __restrict__ f =
            reinterpret_cast<const float4*>(features + (size_t)row * FEAT_DIM);
        const float4* __restrict__ c =
            reinterpret_cast<const float4*>(centers + (size_t)lbl * FEAT_DIM);

        // 256 floats/row = 64 float4; 32 lanes * 2 float4 each.
        float4 f0 = __ldcs(f + lane);          // features: streaming, no reuse
        float4 f1 = __ldcs(f + lane + 32);
        float4 c0 = __ldg(c + lane);           // centers: cached, repeats hit L2
        float4 c1 = __ldg(c + lane + 32);

        float d;
        d = f0.x - c0.x; acc = fmaf(d, d, acc);
        d = f0.y - c0.y; acc = fmaf(d, d, acc);
        d = f0.z - c0.z; acc = fmaf(d, d, acc);
        d = f0.w - c0.w; acc = fmaf(d, d, acc);
        d = f1.x - c1.x; acc = fmaf(d, d, acc);
        d = f1.y - c1.y; acc = fmaf(d, d, acc);
        d = f1.z - c1.z; acc = fmaf(d, d, acc);
        d = f1.w - c1.w; acc = fmaf(d, d, acc);

        row = next_row;
        lbl = next_lbl;
    }

    // warp reduce
    #pragma unroll
    for (int o = 16; o > 0; o >>= 1)
        acc += __shfl_xor_sync(0xFFFFFFFFu, acc, o);

    __shared__ float smem[BLOCK1 / 32];
    if (lane == 0) smem[wid] = acc;
    __syncthreads();

    if (threadIdx.x == 0) {
        float v = 0.0f;
        #pragma unroll
        for (int i = 0; i < BLOCK1 / 32; i++) v += smem[i];
        g_partials[blockIdx.x] = v;                    // plain store
        store_release_gpu_i(&g_flags[blockIdx.x], 1);  // release: partial first
    }
}

__global__ __launch_bounds__(1024) void center_loss_stage2(float* __restrict__ out)
{
    // Runs concurrently with stage1 (trigger fired at stage1 entry).
    const int tid = threadIdx.x;

    float acc = 0.0f;

    // 1176 flags over 1024 threads: thread tid owns {tid} and, for tid<152, {1024+tid}.
    #pragma unroll
    for (int k = 0; k < 2; k++) {
        const int idx = tid + k * 1024;
        if (idx < GRID1) {
            // low-rate poll: relaxed load + sleep backoff (don't steal LTS BW)
            while (load_relaxed_i(&g_flags[idx]) == 0)
                __nanosleep(128);
            acc += g_partials[idx];      // ordered by the fence below before use?
        }
    }
    // One acquire fence orders all the partial reads we just did against the
    // release stores whose flags we observed.
    fence_acquire_gpu();

    // Re-read nothing: the fence must come BEFORE consuming data. Redo the
    // sums from already-ordered memory: simplest correct form is to fence
    // before reading; so fold the fence into the loop exit instead.
    // (acc recomputed below with ordered reads)
    acc = 0.0f;
    #pragma unroll
    for (int k = 0; k < 2; k++) {
        const int idx = tid + k * 1024;
        if (idx < GRID1) {
            acc += g_partials[idx];
            g_flags[idx] = 0;            // reset for next graph replay
        }
    }

    #pragma unroll
    for (int o = 16; o > 0; o >>= 1)
        acc += __shfl_xor_sync(0xFFFFFFFFu, acc, o);

    __shared__ float smem[32];
    if ((tid & 31) == 0) smem[tid >> 5] = acc;
    __syncthreads();

    if (tid < 32) {
        float v = smem[tid];
        #pragma unroll
        for (int o = 16; o > 0; o >>= 1)
            v += __shfl_xor_sync(0xFFFFFFFFu, v, o);
        if (tid == 0)
            out[0] = v * (1.0f / (float)BATCH);   // LAMBDA_C = 1.0
    }
}

extern "C" void kernel_launch(void* const* d_in, const int* in_sizes, int n_in,
                              void* d_out, int out_size)
{
    const float* features = (const float*)d_in[0];
    const int*   labels   = (const int*)  d_in[1];
    const float* centers  = (const float*)d_in[2];
    float*       out      = (float*)d_out;

    center_loss_stage1<<<GRID1, BLOCK1>>>(features, labels, centers);

    cudaLaunchAttribute attrs[1];
    attrs[0].id = cudaLaunchAttributeProgrammaticStreamSerialization;
    attrs[0].val.programmaticStreamSerializationAllowed = 1;

    cudaLaunchConfig_t cfg = {};
    cfg.gridDim  = dim3(1, 1, 1);
    cfg.blockDim = dim3(1024, 1, 1);
    cfg.dynamicSmemBytes = 0;
    cfg.stream   = 0;
    cfg.attrs    = attrs;
    cfg.numAttrs = 1;

    cudaLaunchKernelEx(&cfg, center_loss_stage2, out);
}

// round 14
// speedup vs baseline: 1.0754x; 1.0754x over previous
#include <cuda_runtime.h>
#include <cuda_bf16.h>

// CenterLoss: loss = mean_b sum_d (features[b,d] - centers[labels[b],d])^2
// B=65536, D=256, C=100000. HBM-bound gather + reduction.
// SINGLE kernel: proven R5 mainloop (__ldcs features, pipelined labels, full
// 1184-CTA grid) + fire-and-forget RED.ADD combine into out[0] at CTA exit.
// No stage2 node (saves its ~2.5us exposed launch tail), no last-CTA epilogue,
// no concurrent consumer CTA (three overlap variants each cost ~+2us).
// Replay-safe: CTA0 zeroes out[0] at entry + release flag; every CTA
// acquire-checks the flag once (set ~12us earlier -> single L2 hit) before its
// RED; last CTA (done-counter) resets flags for the next graph replay.

#define BATCH    65536
#define FEAT_DIM 256
#define GRID1    1184          // 148 SMs * 8 CTAs — exact wave-1 fill
#define BLOCK1   256           // 8 warps per CTA
#define NWARPS   ((GRID1 * BLOCK1) >> 5)   // 9472

__device__ int g_zeroflag = 0;             // zero-init at module load
__device__ unsigned int g_done = 0;

__device__ __forceinline__ void store_release_gpu_i(int* p, int v) {
    asm volatile("st.global.release.gpu.s32 [%0], %1;" :: "l"(p), "r"(v) : "memory");
}
__device__ __forceinline__ int load_acquire_gpu_i(const int* p) {
    int v;
    asm volatile("ld.global.acquire.gpu.s32 %0, [%1];" : "=r"(v) : "l"(p) : "memory");
    return v;
}

__global__ __launch_bounds__(BLOCK1, 8) void center_loss_onepass(
    const float* __restrict__ features,
    const int*   __restrict__ labels,
    const float* __restrict__ centers,
    float*       __restrict__ out)
{
    const int lane   = threadIdx.x & 31;
    const int wid    = threadIdx.x >> 5;
    const int warp_g = (blockIdx.x * BLOCK1 + threadIdx.x) >> 5;

    // CTA0 zeroes the (poisoned) output and publishes a release flag.
    // All CTAs' REDs are gated on the flag, so the zero happens-before
    // every accumulation. CTA0 does this at entry, ~12us before any RED.
    if (blockIdx.x == 0 && threadIdx.x == 0) {
        out[0] = 0.0f;
        store_release_gpu_i(&g_zeroflag, 1);
    }

    float acc = 0.0f;

    int row = warp_g;
    int lbl = (row < BATCH) ? __ldcs(labels + row) : 0;   // pipelined label

    for (; row < BATCH; ) {
        const int next_row = row + NWARPS;
        // prefetch next label early — breaks label->address->load serial chain
        const int next_lbl = (next_row < BATCH) ? __ldcs(labels + next_row) : 0;

        const float4* __restrict__ f =
            reinterpret_cast<const float4*>(features + (size_t)row * FEAT_DIM);
        const float4* __restrict__ c =
            reinterpret_cast<const float4*>(centers + (size_t)lbl * FEAT_DIM);

        // 256 floats/row = 64 float4; 32 lanes * 2 float4 each.
        float4 f0 = __ldcs(f + lane);          // features: streaming, no reuse
        float4 f1 = __ldcs(f + lane + 32);
        float4 c0 = __ldg(c + lane);           // centers: cached, repeats hit L2
        float4 c1 = __ldg(c + lane + 32);

        float d;
        d = f0.x - c0.x; acc = fmaf(d, d, acc);
        d = f0.y - c0.y; acc = fmaf(d, d, acc);
        d = f0.z - c0.z; acc = fmaf(d, d, acc);
        d = f0.w - c0.w; acc = fmaf(d, d, acc);
        d = f1.x - c1.x; acc = fmaf(d, d, acc);
        d = f1.y - c1.y; acc = fmaf(d, d, acc);
        d = f1.z - c1.z; acc = fmaf(d, d, acc);
        d = f1.w - c1.w; acc = fmaf(d, d, acc);

        row = next_row;
        lbl = next_lbl;
    }

    // intra-warp reduce
    #pragma unroll
    for (int o = 16; o > 0; o >>= 1)
        acc += __shfl_xor_sync(0xFFFFFFFFu, acc, o);

    __shared__ float smem[BLOCK1 / 32];
    if (lane == 0) smem[wid] = acc;
    __syncthreads();

    if (threadIdx.x == 0) {
        float v = 0.0f;
        #pragma unroll
        for (int i = 0; i < BLOCK1 / 32; i++) v += smem[i];

        // Gate on the zero-flag (acquire): one L2 hit in the common case —
        // the flag was set ~12us ago. Spin only on pathological scheduling.
        while (load_acquire_gpu_i(&g_zeroflag) == 0)
            __nanosleep(64);

        // Fire-and-forget reduction into out[0] (REDG; 0.854 cyc/lane at L2,
        // arrivals spread over the CTA-finish window -> fully pipelined).
        atomicAdd(out, v * (1.0f / (float)BATCH));   // LAMBDA_C = 1.0

        // Last CTA resets the replay state (plain stores; next replay is
        // ordered after this kernel by the stream/graph).
        unsigned int prev = atomicAdd(&g_done, 1u);
        if (prev == GRID1 - 1) {
            g_done = 0;
            g_zeroflag = 0;
        }
    }
}

extern "C" void kernel_launch(void* const* d_in, const int* in_sizes, int n_in,
                              void* d_out, int out_size)
{
    const float* features = (const float*)d_in[0];
    const int*   labels   = (const int*)  d_in[1];
    const float* centers  = (const float*)d_in[2];
    float*       out      = (float*)d_out;

    center_loss_onepass<<<GRID1, BLOCK1>>>(features, labels, centers, out);
}

// round 15
// speedup vs baseline: 1.1699x; 1.0879x over previous
#include <cuda_runtime.h>
#include <cuda_bf16.h>

// CenterLoss: loss = mean_b sum_d (features[b,d] - centers[labels[b],d])^2
// B=65536, D=256, C=100000. HBM-bound gather + reduction.
//
// Structure: [memset node: out[0]=0] -> [single kernel].
// The kernel is the proven R5 mainloop (__ldcs streaming features so gathered
// center rows stay L2-resident; labels software-pipelined; full 1184-CTA
// wave-1 grid) with each CTA's partial folded into out[0] via one fire-and-
// forget atomicAdd. No second kernel node (saves ~2.5us exposed tail), no
// flag gating / acquire loads / done-counters (R14 showed those cost ~1us).
// cudaMemsetAsync is a graph-capturable memset node (not an allocation) and
// stream-orders the zero before every CTA's RED.

#define BATCH    65536
#define FEAT_DIM 256
#define GRID1    1184          // 148 SMs * 8 CTAs — exact wave-1 fill
#define BLOCK1   256           // 8 warps per CTA
#define NWARPS   ((GRID1 * BLOCK1) >> 5)   // 9472

__global__ __launch_bounds__(BLOCK1, 8) void center_loss_onepass(
    const float* __restrict__ features,
    const int*   __restrict__ labels,
    const float* __restrict__ centers,
    float*       __restrict__ out)
{
    const int lane   = threadIdx.x & 31;
    const int wid    = threadIdx.x >> 5;
    const int warp_g = (blockIdx.x * BLOCK1 + threadIdx.x) >> 5;

    float acc = 0.0f;

    int row = warp_g;
    int lbl = (row < BATCH) ? __ldcs(labels + row) : 0;   // pipelined label

    for (; row < BATCH; ) {
        const int next_row = row + NWARPS;
        // prefetch next label early — breaks label->address->load serial chain
        const int next_lbl = (next_row < BATCH) ? __ldcs(labels + next_row) : 0;

        const float4* __restrict__ f =
            reinterpret_cast<const float4*>(features + (size_t)row * FEAT_DIM);
        const float4* __restrict__ c =
            reinterpret_cast<const float4*>(centers + (size_t)lbl * FEAT_DIM);

        // 256 floats/row = 64 float4; 32 lanes * 2 float4 each.
        float4 f0 = __ldcs(f + lane);          // features: streaming, no reuse
        float4 f1 = __ldcs(f + lane + 32);
        float4 c0 = __ldg(c + lane);           // centers: cached, repeats hit L2
        float4 c1 = __ldg(c + lane + 32);

        float d;
        d = f0.x - c0.x; acc = fmaf(d, d, acc);
        d = f0.y - c0.y; acc = fmaf(d, d, acc);
        d = f0.z - c0.z; acc = fmaf(d, d, acc);
        d = f0.w - c0.w; acc = fmaf(d, d, acc);
        d = f1.x - c1.x; acc = fmaf(d, d, acc);
        d = f1.y - c1.y; acc = fmaf(d, d, acc);
        d = f1.z - c1.z; acc = fmaf(d, d, acc);
        d = f1.w - c1.w; acc = fmaf(d, d, acc);

        row = next_row;
        lbl = next_lbl;
    }

    // intra-warp reduce
    #pragma unroll
    for (int o = 16; o > 0; o >>= 1)
        acc += __shfl_xor_sync(0xFFFFFFFFu, acc, o);

    __shared__ float smem[BLOCK1 / 32];
    if (lane == 0) smem[wid] = acc;
    __syncthreads();

    if (threadIdx.x == 0) {
        float v = 0.0f;
        #pragma unroll
        for (int i = 0; i < BLOCK1 / 32; i++) v += smem[i];

        // Fire-and-forget single-address reduction (REDG): 0.854 cyc/op,
        // arrivals spread across the CTA-finish window -> fully pipelined.
        atomicAdd(out, v * (1.0f / (float)BATCH));   // LAMBDA_C = 1.0
    }
}

extern "C" void kernel_launch(void* const* d_in, const int* in_sizes, int n_in,
                              void* d_out, int out_size)
{
    const float* features = (const float*)d_in[0];
    const int*   labels   = (const int*)  d_in[1];
    const float* centers  = (const float*)d_in[2];
    float*       out      = (float*)d_out;

    // Zero the poisoned output as a graph memset node (stream-ordered before
    // the kernel; not a device allocation).
    cudaMemsetAsync(out, 0, sizeof(float), 0);

    center_loss_onepass<<<GRID1, BLOCK1>>>(features, labels, centers, out);
}